// round 3
// baseline (speedup 1.0000x reference)
#include <cuda_runtime.h>
#include <cstdint>
#include <math.h>

#define NLEV 24
#define CAPACITY (1u << 18)
#define BLOCK 128

union F2U { float2 f; unsigned long long u; };

// Packed dual-lane FMA: d = a*b + c on both f32 lanes (Blackwell FFMA2).
__device__ __forceinline__ float2 ffma2(float2 a, float2 b, float2 c) {
    F2U A, B, C, D;
    A.f = a; B.f = b; C.f = c;
    asm("fma.rn.f32x2 %0, %1, %2, %3;" : "=l"(D.u) : "l"(A.u), "l"(B.u), "l"(C.u));
    return D.f;
}
__device__ __forceinline__ float2 f2(float a, float b) { return make_float2(a, b); }

// Branch-free exact-GELU via Abramowitz-Stegun 7.1.26 erf (|err| <= ~1.5e-7 abs).
__device__ __forceinline__ float gelu_fast(float v) {
    const float z  = v * 0.70710678118654752f;
    const float az = fabsf(z);
    const float t  = __fdividef(1.0f, fmaf(0.3275911f, az, 1.0f));
    float p = fmaf(1.061405429f, t, -1.453152027f);
    p = fmaf(p, t, 1.421413741f);
    p = fmaf(p, t, -0.284496736f);
    p = fmaf(p, t, 0.254829592f);
    p *= t;
    const float e  = __expf(-az * az);
    const float er = copysignf(fmaf(-p, e, 1.0f), z);
    return 0.5f * v * (1.0f + er);
}

// Compute one level's lattice: barycentric weights (window folded in) and
// ISSUE the 4 hash-table gathers. Loads are consumed later (software pipeline).
__device__ __forceinline__ void level_setup(
    int lev, float p0, float p1, float p2,
    const float* __restrict__ s_invsc,
    const float* __restrict__ s_shift,
    const float* __restrict__ s_win,
    const float2* __restrict__ tables,
    float2 g[4], float wgt[4])
{
    const float SF0 = 2.30940107675850341796875f;  // 4*sqrt(2/3)/sqrt(1*2)
    const float SF1 = 1.33333333333333333f;
    const float SF2 = 0.94280904158206336f;

    const float inv  = s_invsc[lev];
    const float pos0 = fmaf(p0, inv, s_shift[lev * 3 + 0]);
    const float pos1 = fmaf(p1, inv, s_shift[lev * 3 + 1]);
    const float pos2 = fmaf(p2, inv, s_shift[lev * 3 + 2]);
    const float cf0 = pos0 * SF0, cf1 = pos1 * SF1, cf2 = pos2 * SF2;

    const float S2 = cf2;
    const float S1 = cf2 + cf1;
    const float S0 = S1 + cf0;

    float e[4];
    e[0] = S0;
    e[1] = S1 - cf0;
    e[2] = S2 - 2.0f * cf1;
    e[3] = -3.0f * cf2;

    float r[4];
    #pragma unroll
    for (int i = 0; i < 4; i++) r[i] = rintf(e[i] * 0.25f) * 4.0f;

    const int sumv = (int)rintf((r[0] + r[1] + r[2] + r[3]) * 0.25f);

    float d[4];
    #pragma unroll
    for (int i = 0; i < 4; i++) d[i] = e[i] - r[i];

    // rank = stable argsort(argsort(-diff)) + sum_
    int rk[4];
    #pragma unroll
    for (int i = 0; i < 4; i++) {
        int c = sumv;
        #pragma unroll
        for (int j = 0; j < 4; j++)
            c += (d[j] > d[i] || (d[j] == d[i] && j < i)) ? 1 : 0;
        rk[i] = c;
    }
    #pragma unroll
    for (int i = 0; i < 4; i++) {
        if (rk[i] < 0)      { rk[i] += 4; r[i] += 4.0f; }
        else if (rk[i] > 3) { rk[i] -= 4; r[i] -= 4.0f; }
    }

    float del[4];
    #pragma unroll
    for (int i = 0; i < 4; i++) del[i] = (e[i] - r[i]) * 0.25f;

    // barycentric weights
    float bq0 = 0.f, bq1 = 0.f, bq2 = 0.f, bq3 = 0.f, bq4 = 0.f;
    #pragma unroll
    for (int i = 0; i < 4; i++) {
        const int id = 3 - rk[i];
        const float dv = del[i];
        if (id == 0)      { bq0 += dv; bq1 -= dv; }
        else if (id == 1) { bq1 += dv; bq2 -= dv; }
        else if (id == 2) { bq2 += dv; bq3 -= dv; }
        else              { bq3 += dv; bq4 -= dv; }
    }
    const float wl = s_win[lev];   // fold window into the weights
    wgt[0] = (bq0 + 1.0f + bq4) * wl;
    wgt[1] = bq1 * wl;
    wgt[2] = bq2 * wl;
    wgt[3] = bq3 * wl;

    const int c0 = (int)r[0], c1 = (int)r[1], c2 = (int)r[2];
    const float2* tab = tables + (size_t)lev * CAPACITY;

    #pragma unroll
    for (int k = 0; k < 4; k++) {
        const uint32_t k0 = (uint32_t)(c0 + k - ((rk[0] > 3 - k) ? 4 : 0));
        const uint32_t k1 = (uint32_t)(c1 + k - ((rk[1] > 3 - k) ? 4 : 0));
        const uint32_t k2 = (uint32_t)(c2 + k - ((rk[2] > 3 - k) ? 4 : 0));
        const uint32_t h = k0 ^ (k1 * 2654435761u) ^ (k2 * 805459861u);
        g[k] = __ldg(tab + (h & (CAPACITY - 1u)));
    }
}

__global__ __launch_bounds__(BLOCK, 4)
void sdf_kernel(const float* __restrict__ points,
                const int*   __restrict__ iter_nr,
                const float* __restrict__ tables,
                const float* __restrict__ shifts,
                const float* __restrict__ w1, const float* __restrict__ b1,
                const float* __restrict__ w2, const float* __restrict__ b2,
                const float* __restrict__ w3, const float* __restrict__ b3,
                const float* __restrict__ w4, const float* __restrict__ b4,
                float* __restrict__ out, int N)
{
    __shared__ float4 s_w1[51 * 8];
    __shared__ float4 s_w2[32 * 8];
    __shared__ float4 s_w3[32 * 8];
    __shared__ float4 s_w4g[32 * 8];    // geom cols 1..32, row stride 8xfloat4
    __shared__ float  s_w4s[32];        // sdf column 0
    __shared__ float2 s_b1[16];
    __shared__ float2 s_b2[16];
    __shared__ float2 s_b3[16];
    __shared__ float  s_b4[33];
    __shared__ float  s_shift[NLEV * 3];
    __shared__ float  s_invsc[NLEV];
    __shared__ float  s_win[NLEV];
    __shared__ int    s_nlev;
    __shared__ float  s_stage[BLOCK * 33]; // geom staging (stride 33: conflict-free)

    const int tid = threadIdx.x;

    // ---- cooperative shared load of weights / constants ----
    {
        const float4* g1 = (const float4*)w1;
        const float4* g2 = (const float4*)w2;
        const float4* g3 = (const float4*)w3;
        for (int i = tid; i < 51 * 8; i += BLOCK) s_w1[i] = g1[i];
        for (int i = tid; i < 32 * 8; i += BLOCK) s_w2[i] = g2[i];
        for (int i = tid; i < 32 * 8; i += BLOCK) s_w3[i] = g3[i];
    }
    {
        float* w4g = (float*)s_w4g;
        for (int i = tid; i < 32 * 33; i += BLOCK) {
            int r = i / 33, c = i - r * 33;
            float v = w4[i];
            if (c == 0) s_w4s[r] = v; else w4g[r * 32 + (c - 1)] = v;
        }
    }
    if (tid < 16) {
        s_b1[tid] = ((const float2*)b1)[tid];
        s_b2[tid] = ((const float2*)b2)[tid];
        s_b3[tid] = ((const float2*)b3)[tid];
    }
    if (tid < 33) s_b4[tid] = b4[tid];
    if (tid < NLEV * 3) s_shift[tid] = shifts[tid];
    if (tid < NLEV) {
        // SCALES = geomspace(1, 1e-4, 24) = 10^(i * (-4/23)) in float64 -> f32
        double step = -4.0 / 23.0;
        float sc = (float)pow(10.0, step * (double)tid);
        s_invsc[tid] = 1.0f / sc;
        float t = fminf(fmaxf((float)iter_nr[0] / 10000.0f, 0.0f), 1.0f);
        float alpha = (0.3f + 0.7f * t) * (float)NLEV;
        float x = fminf(fmaxf(alpha - (float)tid, 0.0f), 1.0f);
        s_win[tid] = 0.5f * (1.0f - cosf(3.14159265358979323846f * x));
        if (tid == 0) {
            int na = (int)ceilf(alpha);
            if (na > NLEV) na = NLEV;
            if (na < 0) na = 0;
            s_nlev = na;
        }
    }
    __syncthreads();

    const int n = blockIdx.x * BLOCK + tid;
    const bool active = (n < N);
    const int nlev = s_nlev;

    float  acc0;        // sdf
    float2 accg[16];    // geom 1..32

    if (active) {
        const float p0 = __ldg(points + n * 3 + 0);
        const float p1 = __ldg(points + n * 3 + 1);
        const float p2 = __ldg(points + n * 3 + 2);
        const float2* tab2 = (const float2*)tables;

        // ---- layer-1 accumulator, seeded with bias + point*0.001 rows (48..50)
        float2 h1[16];
        {
            const float2 xa = f2(p0 * 0.001f, p0 * 0.001f);
            const float2 xb = f2(p1 * 0.001f, p1 * 0.001f);
            const float2 xc = f2(p2 * 0.001f, p2 * 0.001f);
            const float4* wa = s_w1 + 48 * 8;
            const float4* wb = s_w1 + 49 * 8;
            const float4* wc = s_w1 + 50 * 8;
            #pragma unroll
            for (int q = 0; q < 8; q++) {
                float4 A = wa[q], B = wb[q], C = wc[q];
                float2 v0 = ffma2(xa, f2(A.x, A.y), s_b1[2*q]);
                v0 = ffma2(xb, f2(B.x, B.y), v0);
                h1[2*q] = ffma2(xc, f2(C.x, C.y), v0);
                float2 v1 = ffma2(xa, f2(A.z, A.w), s_b1[2*q+1]);
                v1 = ffma2(xb, f2(B.z, B.w), v1);
                h1[2*q+1] = ffma2(xc, f2(C.z, C.w), v1);
            }
        }

        // ---- permutohedral encoding: software-pipelined gathers ----
        float2 g[4]; float wg[4];
        if (nlev > 0)
            level_setup(0, p0, p1, p2, s_invsc, s_shift, s_win, tab2, g, wg);

        #pragma unroll 1
        for (int lev = 0; lev < nlev; ++lev) {
            float2 gn[4]; float wn[4];
            if (lev + 1 < nlev)
                level_setup(lev + 1, p0, p1, p2, s_invsc, s_shift, s_win, tab2, gn, wn);

            // consume current level's gathers
            float2 fe = f2(0.0f, 0.0f);
            #pragma unroll
            for (int k = 0; k < 4; k++)
                fe = ffma2(f2(wg[k], wg[k]), g[k], fe);

            const float2 f02 = f2(fe.x, fe.x);
            const float2 f12 = f2(fe.y, fe.y);

            // accumulate into layer-1 hidden: rows 2*lev, 2*lev+1 of w1
            const float4* ra = s_w1 + (2 * lev) * 8;
            #pragma unroll
            for (int q = 0; q < 8; q++) {
                float4 A = ra[q];       // row 2*lev
                float4 B = ra[q + 8];   // row 2*lev+1
                float2 v0 = ffma2(f02, f2(A.x, A.y), h1[2*q]);
                h1[2*q] = ffma2(f12, f2(B.x, B.y), v0);
                float2 v1 = ffma2(f02, f2(A.z, A.w), h1[2*q+1]);
                h1[2*q+1] = ffma2(f12, f2(B.z, B.w), v1);
            }

            #pragma unroll
            for (int k = 0; k < 4; k++) { g[k] = gn[k]; wg[k] = wn[k]; }
        }

        // ---- MLP ----
        #pragma unroll
        for (int q = 0; q < 16; q++) {
            h1[q].x = gelu_fast(h1[q].x);
            h1[q].y = gelu_fast(h1[q].y);
        }

        float2 h2[16];
        #pragma unroll
        for (int q = 0; q < 16; q++) h2[q] = s_b2[q];
        #pragma unroll
        for (int i = 0; i < 16; i++) {
            const float x0 = h1[i].x, x1 = h1[i].y;
            const float2 xa = f2(x0, x0);
            const float2 xb = f2(x1, x1);
            const float4* wr0 = s_w2 + (2 * i) * 8;
            const float4* wr1 = wr0 + 8;
            #pragma unroll
            for (int q = 0; q < 8; q++) {
                float4 A = wr0[q], B = wr1[q];
                float2 v0 = ffma2(xa, f2(A.x, A.y), h2[2*q]);
                h2[2*q] = ffma2(xb, f2(B.x, B.y), v0);
                float2 v1 = ffma2(xa, f2(A.z, A.w), h2[2*q+1]);
                h2[2*q+1] = ffma2(xb, f2(B.z, B.w), v1);
            }
        }
        #pragma unroll
        for (int q = 0; q < 16; q++) {
            h2[q].x = gelu_fast(h2[q].x);
            h2[q].y = gelu_fast(h2[q].y);
        }

        // layer 3 back into h1
        #pragma unroll
        for (int q = 0; q < 16; q++) h1[q] = s_b3[q];
        #pragma unroll
        for (int i = 0; i < 16; i++) {
            const float x0 = h2[i].x, x1 = h2[i].y;
            const float2 xa = f2(x0, x0);
            const float2 xb = f2(x1, x1);
            const float4* wr0 = s_w3 + (2 * i) * 8;
            const float4* wr1 = wr0 + 8;
            #pragma unroll
            for (int q = 0; q < 8; q++) {
                float4 A = wr0[q], B = wr1[q];
                float2 v0 = ffma2(xa, f2(A.x, A.y), h1[2*q]);
                h1[2*q] = ffma2(xb, f2(B.x, B.y), v0);
                float2 v1 = ffma2(xa, f2(A.z, A.w), h1[2*q+1]);
                h1[2*q+1] = ffma2(xb, f2(B.z, B.w), v1);
            }
        }
        #pragma unroll
        for (int q = 0; q < 16; q++) {
            h1[q].x = gelu_fast(h1[q].x);
            h1[q].y = gelu_fast(h1[q].y);
        }

        // layer 4
        acc0 = s_b4[0];
        #pragma unroll
        for (int q = 0; q < 16; q++)
            accg[q] = f2(s_b4[1 + 2 * q], s_b4[2 + 2 * q]);
        #pragma unroll
        for (int i = 0; i < 16; i++) {
            const float x0 = h1[i].x, x1 = h1[i].y;
            const float2 xa = f2(x0, x0);
            const float2 xb = f2(x1, x1);
            const float4* wr0 = s_w4g + (2 * i) * 8;
            const float4* wr1 = wr0 + 8;
            acc0 = fmaf(x0, s_w4s[2 * i], acc0);
            acc0 = fmaf(x1, s_w4s[2 * i + 1], acc0);
            #pragma unroll
            for (int q = 0; q < 8; q++) {
                float4 A = wr0[q], B = wr1[q];
                float2 v0 = ffma2(xa, f2(A.x, A.y), accg[2*q]);
                accg[2*q] = ffma2(xb, f2(B.x, B.y), v0);
                float2 v1 = ffma2(xa, f2(A.z, A.w), accg[2*q+1]);
                accg[2*q+1] = ffma2(xb, f2(B.z, B.w), v1);
            }
        }

        // sdf (coalesced across warp)
        out[n] = acc0;

        // stage geom in smem for coalesced write (stride 33: conflict-free)
        #pragma unroll
        for (int q = 0; q < 16; q++) {
            s_stage[tid * 33 + 2 * q]     = accg[q].x;
            s_stage[tid * 33 + 2 * q + 1] = accg[q].y;
        }
    }

    __syncthreads();

    // coalesced geom writeback
    const int blockBase = blockIdx.x * BLOCK;
    int nvalid = N - blockBase;
    if (nvalid > BLOCK) nvalid = BLOCK;
    if (nvalid > 0) {
        float* gout = out + (size_t)N + (size_t)blockBase * 32;
        for (int i = tid; i < nvalid * 32; i += BLOCK) {
            const int row = i >> 5;
            const int col = i & 31;
            gout[i] = s_stage[row * 33 + col];
        }
    }
}

extern "C" void kernel_launch(void* const* d_in, const int* in_sizes, int n_in,
                              void* d_out, int out_size)
{
    const float* points = (const float*)d_in[0];
    const int*   iter   = (const int*)  d_in[1];
    const float* tables = (const float*)d_in[2];
    const float* shifts = (const float*)d_in[3];
    const float* w1 = (const float*)d_in[4];  const float* b1 = (const float*)d_in[5];
    const float* w2 = (const float*)d_in[6];  const float* b2 = (const float*)d_in[7];
    const float* w3 = (const float*)d_in[8];  const float* b3 = (const float*)d_in[9];
    const float* w4 = (const float*)d_in[10]; const float* b4 = (const float*)d_in[11];

    const int N = in_sizes[0] / 3;
    const int grid = (N + BLOCK - 1) / BLOCK;
    sdf_kernel<<<grid, BLOCK>>>(points, iter, tables, shifts,
                                w1, b1, w2, b2, w3, b3, w4, b4,
                                (float*)d_out, N);
}